// round 4
// baseline (speedup 1.0000x reference)
#include <cuda_runtime.h>

#define BB 32
#define NN 1024
#define DD 512
#define BN (BB * NN)          // 32768 rows
#define OUT_ELEMS (BN * DD)   // 16777216
#define LN_EPS 1e-5f

// Scratch (allocation-free rule: static __device__ arrays)
__device__ float g_S[BN * DD];     // Ax + x
__device__ float g_X[BN * DD];     // layer activations
__device__ float g_denom[BN];
__device__ float g_mask[BN];

// ---------------------------------------------------------------------------
// denom = rowsum(adj) + 1 ; stash rowsum into g_mask (finalized by colsum)
// One warp per row; 8 float4 loads per lane-row.
__global__ void rowsum_kernel(const float* __restrict__ adj) {
    int warp = (blockIdx.x * blockDim.x + threadIdx.x) >> 5;
    int lane = threadIdx.x & 31;
    if (warp >= BN) return;
    const float* p = adj + (size_t)warp * NN;
    float s = 0.f;
    #pragma unroll
    for (int it = 0; it < 8; it++) {
        float4 v = *(const float4*)&p[it * 128 + lane * 4];
        s += v.x + v.y + v.z + v.w;
    }
    #pragma unroll
    for (int o = 16; o > 0; o >>= 1) s += __shfl_down_sync(0xffffffffu, s, o);
    if (lane == 0) {
        g_denom[warp] = s + 1.0f;
        g_mask[warp]  = s;            // temp: rowsum
    }
}

// colsum + mask finalize: mask = ((rowsum + colsum) == 0)
__global__ void colsum_mask_kernel(const float* __restrict__ adj) {
    int idx = blockIdx.x * blockDim.x + threadIdx.x;   // b*NN + n
    if (idx >= BN) return;
    int b = idx >> 10, n = idx & (NN - 1);
    const float* p = adj + (size_t)b * NN * NN + n;
    float c0 = 0.f, c1 = 0.f, c2 = 0.f, c3 = 0.f;
    #pragma unroll 4
    for (int m = 0; m < NN; m += 4) {
        c0 += p[(size_t)(m + 0) * NN];
        c1 += p[(size_t)(m + 1) * NN];
        c2 += p[(size_t)(m + 2) * NN];
        c3 += p[(size_t)(m + 3) * NN];
    }
    float cs = (c0 + c1) + (c2 + c3);
    g_mask[idx] = ((g_mask[idx] + cs) == 0.0f) ? 1.0f : 0.0f;
}

// ---------------------------------------------------------------------------
// GEMM1: S[b] = adj[b] @ X[b] + X[b]
// 128x128x8 tile, 256 threads, 8x8 per thread, register-prefetched loads.
__global__ __launch_bounds__(256)
void gemm1_kernel(const float* __restrict__ adj,
                  const float* __restrict__ Xext,
                  int use_internal) {
    __shared__ float As[8][128];
    __shared__ float Bs[8][128];

    const float* Xin = use_internal ? g_X : Xext;
    int b  = blockIdx.z;
    const float* A  = adj + (size_t)b * NN * NN;
    const float* Bm = Xin + (size_t)b * NN * DD;
    int ti = blockIdx.y * 128, tj = blockIdx.x * 128;
    int tid  = threadIdx.x;
    int arow = tid >> 1,  akq = (tid & 1) * 4;        // A: 128 rows x 8 K
    int brow = tid >> 5,  bjq = (tid & 31) * 4;       // B: 8 K x 128 cols
    int tx   = tid & 15,  ty  = tid >> 4;

    float acc[8][8] = {};

    const float* ap = &A[(size_t)(ti + arow) * NN + akq];
    const float* bp = &Bm[(size_t)brow * DD + tj + bjq];
    float4 av = *(const float4*)ap;
    float4 bv = *(const float4*)bp;

    for (int k0 = 0; k0 < NN; k0 += 8) {
        __syncthreads();
        As[akq + 0][arow] = av.x; As[akq + 1][arow] = av.y;
        As[akq + 2][arow] = av.z; As[akq + 3][arow] = av.w;
        *(float4*)&Bs[brow][bjq] = bv;
        __syncthreads();

        if (k0 + 8 < NN) {                             // prefetch next tile
            av = *(const float4*)(ap + (k0 + 8));
            bv = *(const float4*)(bp + (size_t)(k0 + 8) * DD);
        }

        #pragma unroll
        for (int kk = 0; kk < 8; kk++) {
            float a[8], c[8];
            *(float4*)&a[0] = *(const float4*)&As[kk][ty * 8];
            *(float4*)&a[4] = *(const float4*)&As[kk][ty * 8 + 4];
            *(float4*)&c[0] = *(const float4*)&Bs[kk][tx * 8];
            *(float4*)&c[4] = *(const float4*)&Bs[kk][tx * 8 + 4];
            #pragma unroll
            for (int i = 0; i < 8; i++)
                #pragma unroll
                for (int j = 0; j < 8; j++)
                    acc[i][j] += a[i] * c[j];
        }
    }

    // epilogue: + residual x, store to g_S
    float* Sb = g_S + (size_t)b * NN * DD;
    #pragma unroll
    for (int i = 0; i < 8; i++) {
        int r = ti + ty * 8 + i;
        #pragma unroll
        for (int jq = 0; jq < 2; jq++) {
            int cc = tj + tx * 8 + jq * 4;
            float4 res = *(const float4*)&Bm[(size_t)r * DD + cc];
            float4 o;
            o.x = acc[i][jq * 4 + 0] + res.x;
            o.y = acc[i][jq * 4 + 1] + res.y;
            o.z = acc[i][jq * 4 + 2] + res.z;
            o.w = acc[i][jq * 4 + 3] + res.w;
            *(float4*)&Sb[(size_t)r * DD + cc] = o;
        }
    }
}

// ---------------------------------------------------------------------------
// GEMM2: g_X = relu((g_S @ W^T + 2*bias) / denom)
// [BN x 512] @ [512 x 512]^T, same tiling.
__global__ __launch_bounds__(256)
void gemm2_kernel(const float* __restrict__ W,
                  const float* __restrict__ bias) {
    __shared__ float As[8][128];
    __shared__ float Bs[8][128];

    int ti = blockIdx.y * 128, tj = blockIdx.x * 128;
    int tid  = threadIdx.x;
    int arow = tid >> 1, akq = (tid & 1) * 4;
    int tx   = tid & 15, ty  = tid >> 4;

    float acc[8][8] = {};

    const float* ap = &g_S[(size_t)(ti + arow) * DD + akq];
    const float* wp = &W[(size_t)(tj + arow) * DD + akq];
    float4 av = *(const float4*)ap;
    float4 wv = *(const float4*)wp;

    for (int k0 = 0; k0 < DD; k0 += 8) {
        __syncthreads();
        As[akq + 0][arow] = av.x; As[akq + 1][arow] = av.y;
        As[akq + 2][arow] = av.z; As[akq + 3][arow] = av.w;
        Bs[akq + 0][arow] = wv.x; Bs[akq + 1][arow] = wv.y;
        Bs[akq + 2][arow] = wv.z; Bs[akq + 3][arow] = wv.w;
        __syncthreads();

        if (k0 + 8 < DD) {
            av = *(const float4*)(ap + (k0 + 8));
            wv = *(const float4*)(wp + (k0 + 8));
        }

        #pragma unroll
        for (int kk = 0; kk < 8; kk++) {
            float a[8], c[8];
            *(float4*)&a[0] = *(const float4*)&As[kk][ty * 8];
            *(float4*)&a[4] = *(const float4*)&As[kk][ty * 8 + 4];
            *(float4*)&c[0] = *(const float4*)&Bs[kk][tx * 8];
            *(float4*)&c[4] = *(const float4*)&Bs[kk][tx * 8 + 4];
            #pragma unroll
            for (int i = 0; i < 8; i++)
                #pragma unroll
                for (int j = 0; j < 8; j++)
                    acc[i][j] += a[i] * c[j];
        }
    }

    #pragma unroll
    for (int i = 0; i < 8; i++) {
        int m = ti + ty * 8 + i;
        float rden = 1.0f / g_denom[m];
        #pragma unroll
        for (int jq = 0; jq < 2; jq++) {
            int n = tj + tx * 8 + jq * 4;
            float4 bi = *(const float4*)&bias[n];
            float4 o;
            o.x = fmaxf((acc[i][jq * 4 + 0] + 2.0f * bi.x) * rden, 0.0f);
            o.y = fmaxf((acc[i][jq * 4 + 1] + 2.0f * bi.y) * rden, 0.0f);
            o.z = fmaxf((acc[i][jq * 4 + 2] + 2.0f * bi.z) * rden, 0.0f);
            o.w = fmaxf((acc[i][jq * 4 + 3] + 2.0f * bi.w) * rden, 0.0f);
            *(float4*)&g_X[(size_t)m * DD + n] = o;
        }
    }
}

// ---------------------------------------------------------------------------
// LayerNorm over last dim (512), one block (128 threads) per row, g_X -> out
__global__ void ln_kernel(const float* __restrict__ gamma,
                          const float* __restrict__ beta,
                          float* __restrict__ out) {
    int row = blockIdx.x;
    int t   = threadIdx.x;          // 0..127
    const float* p = g_X + (size_t)row * DD;
    float4 v = *(const float4*)&p[t * 4];

    __shared__ float sm[4];
    __shared__ float s_mu, s_rstd;

    float s = v.x + v.y + v.z + v.w;
    #pragma unroll
    for (int o = 16; o > 0; o >>= 1) s += __shfl_down_sync(0xffffffffu, s, o);
    if ((t & 31) == 0) sm[t >> 5] = s;
    __syncthreads();
    if (t == 0) s_mu = (sm[0] + sm[1] + sm[2] + sm[3]) * (1.0f / DD);
    __syncthreads();

    float mu = s_mu;
    float dx = v.x - mu, dy = v.y - mu, dz = v.z - mu, dw = v.w - mu;
    float q = dx * dx + dy * dy + dz * dz + dw * dw;
    #pragma unroll
    for (int o = 16; o > 0; o >>= 1) q += __shfl_down_sync(0xffffffffu, q, o);
    if ((t & 31) == 0) sm[t >> 5] = q;
    __syncthreads();
    if (t == 0)
        s_rstd = rsqrtf((sm[0] + sm[1] + sm[2] + sm[3]) * (1.0f / DD) + LN_EPS);
    __syncthreads();

    float r = s_rstd;
    float4 ga = *(const float4*)&gamma[t * 4];
    float4 be = *(const float4*)&beta[t * 4];
    float4 o;
    o.x = dx * r * ga.x + be.x;
    o.y = dy * r * ga.y + be.y;
    o.z = dz * r * ga.z + be.z;
    o.w = dw * r * ga.w + be.w;
    *(float4*)&out[(size_t)row * DD + t * 4] = o;
}

// Optional mask tail (if the harness output includes the masks tensor)
__global__ void mask_out_kernel(float* __restrict__ out, int count) {
    int i = blockIdx.x * blockDim.x + threadIdx.x;
    if (i < count) out[(size_t)OUT_ELEMS + i] = (i < BN) ? g_mask[i] : 0.0f;
}

// ---------------------------------------------------------------------------
extern "C" void kernel_launch(void* const* d_in, const int* in_sizes, int n_in,
                              void* d_out, int out_size) {
    const float* adj = (const float*)d_in[0];
    const float* x0  = (const float*)d_in[1];
    // d_in[2] = seq_lens (all == N, unused)
    const float* W0w = (const float*)d_in[3];
    const float* W0b = (const float*)d_in[4];
    const float* W1w = (const float*)d_in[5];
    const float* W1b = (const float*)d_in[6];
    const float* lng = (const float*)d_in[7];
    const float* lnb = (const float*)d_in[8];
    float* out = (float*)d_out;

    // denom + mask
    rowsum_kernel<<<(BN * 32 + 255) / 256, 256>>>(adj);
    colsum_mask_kernel<<<BN / 256, 256>>>(adj);

    dim3 grid1(DD / 128, NN / 128, BB);     // 4 x 8 x 32
    dim3 grid2(DD / 128, BN / 128);         // 4 x 256

    // Layer 0
    gemm1_kernel<<<grid1, 256>>>(adj, x0, 0);
    gemm2_kernel<<<grid2, 256>>>(W0w, W0b);
    // Layer 1
    gemm1_kernel<<<grid1, 256>>>(adj, x0 /*unused*/, 1);
    gemm2_kernel<<<grid2, 256>>>(W1w, W1b);

    // LayerNorm -> output
    ln_kernel<<<BN, 128>>>(lng, lnb, out);

    // Mask tail if present in output buffer
    int tail = out_size - OUT_ELEMS;
    if (tail > 0)
        mask_out_kernel<<<(tail + 255) / 256, 256>>>(out, tail);
}

// round 8
// speedup vs baseline: 2.2545x; 2.2545x over previous
#include <cuda_runtime.h>
#include <cuda_bf16.h>
#include <cstdint>

#define BB 32
#define NN 1024
#define DD 512
#define BN (BB * NN)          // 32768 rows
#define OUT_ELEMS (BN * DD)   // 16777216
#define LN_EPS 1e-5f

// ---------------------------------------------------------------------------
// Device scratch (allocation-free rule). Referenced ONLY from device code.
__device__ __align__(128) __nv_bfloat16 g_adj_h[(size_t)BB * NN * NN];
__device__ __align__(128) __nv_bfloat16 g_adj_l[(size_t)BB * NN * NN];
__device__ __align__(128) __nv_bfloat16 g_Xt_h[(size_t)BB * DD * NN];   // [b][512 n][1024 k]
__device__ __align__(128) __nv_bfloat16 g_Xt_l[(size_t)BB * DD * NN];
__device__ __align__(128) __nv_bfloat16 g_S_h[(size_t)BN * DD];
__device__ __align__(128) __nv_bfloat16 g_S_l[(size_t)BN * DD];
__device__ __align__(128) __nv_bfloat16 g_W_h[DD * DD];
__device__ __align__(128) __nv_bfloat16 g_W_l[DD * DD];
__device__ __align__(128) float g_X[(size_t)BN * DD];
__device__ float g_denom[BN];
__device__ float g_mask[BN];

// ---------------------------------------------------------------------------
__device__ __forceinline__ uint32_t smem_u32(const void* p) {
    uint32_t a;
    asm("{ .reg .u64 t; cvta.to.shared.u64 t, %1; cvt.u32.u64 %0, t; }" : "=r"(a) : "l"(p));
    return a;
}

__device__ __forceinline__ void ldsm_x4(uint32_t* r, uint32_t addr) {
    asm volatile("ldmatrix.sync.aligned.m8n8.x4.shared.b16 {%0,%1,%2,%3}, [%4];"
                 : "=r"(r[0]), "=r"(r[1]), "=r"(r[2]), "=r"(r[3]) : "r"(addr));
}

__device__ __forceinline__ void mma16816(float* c, const uint32_t* a, const uint32_t* b) {
    asm volatile(
        "mma.sync.aligned.m16n8k16.row.col.f32.bf16.bf16.f32 "
        "{%0,%1,%2,%3}, {%4,%5,%6,%7}, {%8,%9}, {%10,%11,%12,%13};"
        : "=f"(c[0]), "=f"(c[1]), "=f"(c[2]), "=f"(c[3])
        : "r"(a[0]), "r"(a[1]), "r"(a[2]), "r"(a[3]),
          "r"(b[0]), "r"(b[1]),
          "f"(c[0]), "f"(c[1]), "f"(c[2]), "f"(c[3]));
}

__device__ __forceinline__ void split2(float v0, float v1, uint32_t& hp, uint32_t& lp) {
    __nv_bfloat16 h0 = __float2bfloat16(v0);
    __nv_bfloat16 h1 = __float2bfloat16(v1);
    __nv_bfloat16 l0 = __float2bfloat16(v0 - __bfloat162float(h0));
    __nv_bfloat16 l1 = __float2bfloat16(v1 - __bfloat162float(h1));
    hp = (uint32_t)__bfloat16_as_ushort(h0) | ((uint32_t)__bfloat16_as_ushort(h1) << 16);
    lp = (uint32_t)__bfloat16_as_ushort(l0) | ((uint32_t)__bfloat16_as_ushort(l1) << 16);
}

// ---------------------------------------------------------------------------
// denom = rowsum(adj) + 1 ; stash rowsum into g_mask (finalized by colsum)
__global__ void rowsum_kernel(const float* __restrict__ adj) {
    int warp = (blockIdx.x * blockDim.x + threadIdx.x) >> 5;
    int lane = threadIdx.x & 31;
    if (warp >= BN) return;
    const float* p = adj + (size_t)warp * NN;
    float s = 0.f;
    #pragma unroll
    for (int it = 0; it < 8; it++) {
        float4 v = *(const float4*)&p[it * 128 + lane * 4];
        s += v.x + v.y + v.z + v.w;
    }
    #pragma unroll
    for (int o = 16; o > 0; o >>= 1) s += __shfl_down_sync(0xffffffffu, s, o);
    if (lane == 0) {
        g_denom[warp] = s + 1.0f;
        g_mask[warp]  = s;
    }
}

__global__ void colsum_mask_kernel(const float* __restrict__ adj) {
    int idx = blockIdx.x * blockDim.x + threadIdx.x;
    if (idx >= BN) return;
    int b = idx >> 10, n = idx & (NN - 1);
    const float* p = adj + (size_t)b * NN * NN + n;
    float c0 = 0.f, c1 = 0.f, c2 = 0.f, c3 = 0.f;
    #pragma unroll 4
    for (int m = 0; m < NN; m += 4) {
        c0 += p[(size_t)(m + 0) * NN];
        c1 += p[(size_t)(m + 1) * NN];
        c2 += p[(size_t)(m + 2) * NN];
        c3 += p[(size_t)(m + 3) * NN];
    }
    float cs = (c0 + c1) + (c2 + c3);
    g_mask[idx] = ((g_mask[idx] + cs) == 0.0f) ? 1.0f : 0.0f;
}

// ---------------------------------------------------------------------------
// adj f32 -> g_adj_h/g_adj_l (globals referenced in DEVICE code — the R6/R7 bug
// was passing __device__ symbols as host-side kernel args)
__global__ void split_adj_kernel(const float* __restrict__ in) {
    size_t i = (size_t)blockIdx.x * blockDim.x + threadIdx.x;   // float4 index
    float4 v = ((const float4*)in)[i];
    uint2 hv, lv;
    split2(v.x, v.y, hv.x, lv.x);
    split2(v.z, v.w, hv.y, lv.y);
    ((uint2*)g_adj_h)[i] = hv;
    ((uint2*)g_adj_l)[i] = lv;
}

// W f32 -> g_W_h/g_W_l
__global__ void split_W_kernel(const float* __restrict__ in) {
    size_t i = (size_t)blockIdx.x * blockDim.x + threadIdx.x;
    if (i >= (size_t)DD * DD / 4) return;
    float4 v = ((const float4*)in)[i];
    uint2 hv, lv;
    split2(v.x, v.y, hv.x, lv.x);
    split2(v.z, v.w, hv.y, lv.y);
    ((uint2*)g_W_h)[i] = hv;
    ((uint2*)g_W_l)[i] = lv;
}

// X [B][1024 k][512 n] f32 -> g_Xt_h/l [B][512 n][1024 k] bf16 (transpose+split)
__global__ void tsplit_kernel(const float* __restrict__ inExt, int use_internal) {
    const float* in = use_internal ? g_X : inExt;
    __shared__ float tile[32][33];
    int b = blockIdx.z;
    int k0 = blockIdx.x * 32, n0 = blockIdx.y * 32;
    const float* src = in + (size_t)b * NN * DD;
    int tx = threadIdx.x, ty = threadIdx.y;     // (32, 8)
    #pragma unroll
    for (int r = 0; r < 4; r++)
        tile[ty + r * 8][tx] = src[(size_t)(k0 + ty + r * 8) * DD + n0 + tx];
    __syncthreads();
    __nv_bfloat16* oh = g_Xt_h + (size_t)b * DD * NN;
    __nv_bfloat16* ol = g_Xt_l + (size_t)b * DD * NN;
    #pragma unroll
    for (int r = 0; r < 4; r++) {
        int n = n0 + ty + r * 8;
        float v = tile[tx][ty + r * 8];
        __nv_bfloat16 h = __float2bfloat16(v);
        __nv_bfloat16 l = __float2bfloat16(v - __bfloat162float(h));
        oh[(size_t)n * NN + k0 + tx] = h;
        ol[(size_t)n * NN + k0 + tx] = l;
    }
}

// ---------------------------------------------------------------------------
// Unified tensor-core GEMM, bf16 hi/lo 3-pass compensation via mma.sync.
// mode 0 (gemm1): D = adj @ Xt^T ; epilogue S = D + residual -> S_hi/S_lo bf16
// mode 1 (gemm2): D = S @ W^T   ; epilogue g_X = relu((D + 2b)/denom)  f32
// CTA 128x128, K-chunk 32, 8 warps (warp tile 64x32), reg-prefetch pipeline.
#define STRIDE 40

__global__ __launch_bounds__(256, 1)
void mma_gemm_kernel(int mode, const float* __restrict__ resExt, int res_internal,
                     const float* __restrict__ bias) {
    __shared__ __align__(16) __nv_bfloat16 sAh[128 * STRIDE];
    __shared__ __align__(16) __nv_bfloat16 sAl[128 * STRIDE];
    __shared__ __align__(16) __nv_bfloat16 sBh[128 * STRIDE];
    __shared__ __align__(16) __nv_bfloat16 sBl[128 * STRIDE];

    int tid = threadIdx.x, wid = tid >> 5, lane = tid & 31;
    int wm = (wid >> 2) * 64, wn = (wid & 3) * 32;   // warp tile origin
    int grp = lane >> 2, qid = lane & 3;

    const int K = (mode == 0) ? NN : DD;
    const int nchunks = K / 32;
    const int b = blockIdx.z;
    const int grow0 = (blockIdx.z * gridDim.y + blockIdx.y) * 128;   // global out row
    const int col0 = blockIdx.x * 128;

    const __nv_bfloat16 *Ah, *Al, *Bh, *Bl;
    int lda, ldb;
    if (mode == 0) {
        size_t aoff = (size_t)b * NN * NN + (size_t)(blockIdx.y * 128) * NN;
        Ah = g_adj_h + aoff;  Al = g_adj_l + aoff;  lda = NN;
        size_t boff = (size_t)b * DD * NN + (size_t)col0 * NN;
        Bh = g_Xt_h + boff;   Bl = g_Xt_l + boff;   ldb = NN;
    } else {
        size_t aoff = (size_t)grow0 * DD;
        Ah = g_S_h + aoff;    Al = g_S_l + aoff;    lda = DD;
        size_t boff = (size_t)col0 * DD;
        Bh = g_W_h + boff;    Bl = g_W_l + boff;    ldb = DD;
    }

    // global->smem staging: each thread owns (row = tid/2, 16-bf16 half = tid%2)
    const int lrow = tid >> 1;
    const int lcol = (tid & 1) * 16;
    const __nv_bfloat16* pAh = Ah + (size_t)lrow * lda + lcol;
    const __nv_bfloat16* pAl = Al + (size_t)lrow * lda + lcol;
    const __nv_bfloat16* pBh = Bh + (size_t)lrow * ldb + lcol;
    const __nv_bfloat16* pBl = Bl + (size_t)lrow * ldb + lcol;

    // per-thread ldmatrix base addresses
    const int mat = lane >> 3, rr = lane & 7;
    const uint32_t aOffA = (uint32_t)(((wm + (mat & 1) * 8 + rr) * STRIDE + (mat >> 1) * 8) * 2);
    const uint32_t aOffB = (uint32_t)(((wn + (mat >> 1) * 8 + rr) * STRIDE + (mat & 1) * 8) * 2);
    const uint32_t bAh = smem_u32(sAh) + aOffA;
    const uint32_t bAl = smem_u32(sAl) + aOffA;
    const uint32_t bBh = smem_u32(sBh) + aOffB;
    const uint32_t bBl = smem_u32(sBl) + aOffB;

    float acc[4][4][4];
    #pragma unroll
    for (int i = 0; i < 4; i++)
        #pragma unroll
        for (int j = 0; j < 4; j++)
            #pragma unroll
            for (int q = 0; q < 4; q++) acc[i][j][q] = 0.f;

    uint4 p0 = *(const uint4*)pAh,       p1 = *(const uint4*)(pAh + 8);
    uint4 p2 = *(const uint4*)pAl,       p3 = *(const uint4*)(pAl + 8);
    uint4 p4 = *(const uint4*)pBh,       p5 = *(const uint4*)(pBh + 8);
    uint4 p6 = *(const uint4*)pBl,       p7 = *(const uint4*)(pBl + 8);

    for (int ci = 0; ci < nchunks; ci++) {
        __syncthreads();
        *(uint4*)&sAh[lrow * STRIDE + lcol]     = p0;
        *(uint4*)&sAh[lrow * STRIDE + lcol + 8] = p1;
        *(uint4*)&sAl[lrow * STRIDE + lcol]     = p2;
        *(uint4*)&sAl[lrow * STRIDE + lcol + 8] = p3;
        *(uint4*)&sBh[lrow * STRIDE + lcol]     = p4;
        *(uint4*)&sBh[lrow * STRIDE + lcol + 8] = p5;
        *(uint4*)&sBl[lrow * STRIDE + lcol]     = p6;
        *(uint4*)&sBl[lrow * STRIDE + lcol + 8] = p7;
        __syncthreads();

        if (ci + 1 < nchunks) {
            int k0 = (ci + 1) * 32;
            p0 = *(const uint4*)(pAh + k0); p1 = *(const uint4*)(pAh + k0 + 8);
            p2 = *(const uint4*)(pAl + k0); p3 = *(const uint4*)(pAl + k0 + 8);
            p4 = *(const uint4*)(pBh + k0); p5 = *(const uint4*)(pBh + k0 + 8);
            p6 = *(const uint4*)(pBl + k0); p7 = *(const uint4*)(pBl + k0 + 8);
        }

        #pragma unroll
        for (int ks = 0; ks < 2; ks++) {
            const uint32_t kof = (uint32_t)(ks * 32);
            uint32_t ah[4][4], al[4][4], bh[8], bl[8];
            #pragma unroll
            for (int mi = 0; mi < 4; mi++) {
                ldsm_x4(ah[mi], bAh + mi * (16 * STRIDE * 2) + kof);
                ldsm_x4(al[mi], bAl + mi * (16 * STRIDE * 2) + kof);
            }
            ldsm_x4(bh,     bBh + kof);
            ldsm_x4(bh + 4, bBh + 16 * STRIDE * 2 + kof);
            ldsm_x4(bl,     bBl + kof);
            ldsm_x4(bl + 4, bBl + 16 * STRIDE * 2 + kof);

            #pragma unroll
            for (int mi = 0; mi < 4; mi++)
                #pragma unroll
                for (int ni = 0; ni < 4; ni++) {
                    mma16816(acc[mi][ni], ah[mi], &bh[ni * 2]);
                    mma16816(acc[mi][ni], ah[mi], &bl[ni * 2]);
                    mma16816(acc[mi][ni], al[mi], &bh[ni * 2]);
                }
        }
    }

    // Epilogue. Thread owns (rows grp, grp+8) x (cols qid*2, +1) per (mi,ni) tile.
    #pragma unroll
    for (int mi = 0; mi < 4; mi++) {
        #pragma unroll
        for (int h = 0; h < 2; h++) {
            int grow = grow0 + wm + mi * 16 + grp + h * 8;
            if (mode == 0) {
                const float* rbase = res_internal ? g_X : resExt;
                #pragma unroll
                for (int ni = 0; ni < 4; ni++) {
                    int gcol = col0 + wn + ni * 8 + qid * 2;
                    float2 res = *(const float2*)&rbase[(size_t)grow * DD + gcol];
                    uint32_t hp, lp;
                    split2(acc[mi][ni][h * 2 + 0] + res.x,
                           acc[mi][ni][h * 2 + 1] + res.y, hp, lp);
                    *(uint32_t*)&g_S_h[(size_t)grow * DD + gcol] = hp;
                    *(uint32_t*)&g_S_l[(size_t)grow * DD + gcol] = lp;
                }
            } else {
                float rden = 1.0f / g_denom[grow];
                #pragma unroll
                for (int ni = 0; ni < 4; ni++) {
                    int gcol = col0 + wn + ni * 8 + qid * 2;
                    float2 bi = *(const float2*)&bias[gcol];
                    float2 o;
                    o.x = fmaxf((acc[mi][ni][h * 2 + 0] + 2.0f * bi.x) * rden, 0.0f);
                    o.y = fmaxf((acc[mi][ni][h * 2 + 1] + 2.0f * bi.y) * rden, 0.0f);
                    *(float2*)&g_X[(size_t)grow * DD + gcol] = o;
                }
            }
        }
    }
}

// ---------------------------------------------------------------------------
// LayerNorm over last dim (512), one block (128 threads) per row, g_X -> out
__global__ void ln_kernel(const float* __restrict__ gamma,
                          const float* __restrict__ beta,
                          float* __restrict__ out) {
    int row = blockIdx.x;
    int t   = threadIdx.x;
    const float* p = g_X + (size_t)row * DD;
    float4 v = *(const float4*)&p[t * 4];

    __shared__ float sm[4];
    __shared__ float s_mu, s_rstd;

    float s = v.x + v.y + v.z + v.w;
    #pragma unroll
    for (int o = 16; o > 0; o >>= 1) s += __shfl_down_sync(0xffffffffu, s, o);
    if ((t & 31) == 0) sm[t >> 5] = s;
    __syncthreads();
    if (t == 0) s_mu = (sm[0] + sm[1] + sm[2] + sm[3]) * (1.0f / DD);
    __syncthreads();

    float mu = s_mu;
    float dx = v.x - mu, dy = v.y - mu, dz = v.z - mu, dw = v.w - mu;
    float q = dx * dx + dy * dy + dz * dz + dw * dw;
    #pragma unroll
    for (int o = 16; o > 0; o >>= 1) q += __shfl_down_sync(0xffffffffu, q, o);
    if ((t & 31) == 0) sm[t >> 5] = q;
    __syncthreads();
    if (t == 0)
        s_rstd = rsqrtf((sm[0] + sm[1] + sm[2] + sm[3]) * (1.0f / DD) + LN_EPS);
    __syncthreads();

    float r = s_rstd;
    float4 ga = *(const float4*)&gamma[t * 4];
    float4 be = *(const float4*)&beta[t * 4];
    float4 o;
    o.x = dx * r * ga.x + be.x;
    o.y = dy * r * ga.y + be.y;
    o.z = dz * r * ga.z + be.z;
    o.w = dw * r * ga.w + be.w;
    *(float4*)&out[(size_t)row * DD + t * 4] = o;
}

__global__ void mask_out_kernel(float* __restrict__ out, int count) {
    int i = blockIdx.x * blockDim.x + threadIdx.x;
    if (i < count) out[(size_t)OUT_ELEMS + i] = (i < BN) ? g_mask[i] : 0.0f;
}

// ---------------------------------------------------------------------------
extern "C" void kernel_launch(void* const* d_in, const int* in_sizes, int n_in,
                              void* d_out, int out_size) {
    const float* adj = (const float*)d_in[0];
    const float* x0  = (const float*)d_in[1];
    const float* W0w = (const float*)d_in[3];
    const float* W0b = (const float*)d_in[4];
    const float* W1w = (const float*)d_in[5];
    const float* W1b = (const float*)d_in[6];
    const float* lng = (const float*)d_in[7];
    const float* lnb = (const float*)d_in[8];
    float* out = (float*)d_out;

    // denom + mask
    rowsum_kernel<<<(BN * 32 + 255) / 256, 256>>>(adj);
    colsum_mask_kernel<<<BN / 256, 256>>>(adj);

    // bf16 hi/lo conversions (globals written from device code only)
    {
        size_t n4 = (size_t)BB * NN * NN / 4;   // 8388608, divisible by 256
        split_adj_kernel<<<(unsigned)(n4 / 256), 256>>>(adj);
    }
    dim3 tgrid(NN / 32, DD / 32, BB), tblk(32, 8);
    tsplit_kernel<<<tgrid, tblk>>>(x0, 0);
    split_W_kernel<<<(DD * DD / 4 + 255) / 256, 256>>>(W0w);

    dim3 grid1(DD / 128, NN / 128, BB);     // 4 x 8 x 32
    dim3 grid2(DD / 128, BN / 128, 1);      // 4 x 256

    // Layer 0
    mma_gemm_kernel<<<grid1, 256>>>(0, x0, 0, nullptr);
    mma_gemm_kernel<<<grid2, 256>>>(1, nullptr, 0, W0b);

    // Layer 1
    tsplit_kernel<<<tgrid, tblk>>>(nullptr, 1);
    split_W_kernel<<<(DD * DD / 4 + 255) / 256, 256>>>(W1w);
    mma_gemm_kernel<<<grid1, 256>>>(0, nullptr, 1, nullptr);
    mma_gemm_kernel<<<grid2, 256>>>(1, nullptr, 0, W1b);

    // LayerNorm -> output
    ln_kernel<<<BN, 128>>>(lng, lnb, out);

    int tail = out_size - OUT_ELEMS;
    if (tail > 0)
        mask_out_kernel<<<(tail + 255) / 256, 256>>>(out, tail);
}